// round 9
// baseline (speedup 1.0000x reference)
#include <cuda_runtime.h>
#include <cstdint>

// Problem constants
#define B_    4
#define T_    2048
#define C_DIM 1024
#define H_    16
#define D_    64
#define M_ROWS (B_*T_)      // 8192
#define QKV_N  (3*C_DIM)    // 3072
#define NEG_BIG (-3.0e38f)

// Scratch (device globals)
__device__ float g_q[8388608];    // [B,H,T,D]  tf32-prerounded (Q pre-scaled by 1/8)
__device__ float g_k[8388608];
__device__ float g_v[8388608];
__device__ float g_y[8388608];    // fragment-major, tf32-prerounded
__device__ float g_xr[8388608];   // x, fragment-major A-layout, tf32-rounded
__device__ float g_war[3145728];  // w_attn, fragment-major B-layout, tf32-rounded
__device__ float g_wpr[1048576];  // w_proj, fragment-major B-layout, tf32-rounded

// ---------------------------------------------------------------------------
// Helpers
// ---------------------------------------------------------------------------
__device__ __forceinline__ uint32_t cvta_smem(const void* p) {
    uint32_t a;
    asm("{ .reg .u64 t; cvta.to.shared.u64 t, %1; cvt.u32.u64 %0, t; }"
        : "=r"(a) : "l"(p));
    return a;
}
__device__ __forceinline__ void cp_async16(uint32_t dst, const void* src) {
    asm volatile("cp.async.cg.shared.global [%0], [%1], 16;" :: "r"(dst), "l"(src));
}
__device__ __forceinline__ void cp_commit() { asm volatile("cp.async.commit_group;"); }
__device__ __forceinline__ void cp_wait0()  { asm volatile("cp.async.wait_group 0;"); }
__device__ __forceinline__ void cp_wait1()  { asm volatile("cp.async.wait_group 1;"); }
__device__ __forceinline__ void cp_wait2()  { asm volatile("cp.async.wait_group 2;"); }

__device__ __forceinline__ uint32_t tf32_rne(float x) {
    uint32_t y;
    asm("cvt.rna.tf32.f32 %0, %1;" : "=r"(y) : "f"(x));
    return y;
}
__device__ __forceinline__ void mma_tf32(float* d, const uint32_t* a, const uint32_t* b) {
    asm volatile(
        "mma.sync.aligned.m16n8k8.row.col.f32.tf32.tf32.f32 "
        "{%0,%1,%2,%3}, {%4,%5,%6,%7}, {%8,%9}, {%0,%1,%2,%3};"
        : "+f"(d[0]), "+f"(d[1]), "+f"(d[2]), "+f"(d[3])
        : "r"(a[0]), "r"(a[1]), "r"(a[2]), "r"(a[3]), "r"(b[0]), "r"(b[1]));
}

// ---------------------------------------------------------------------------
// Fragment-major permute+round pre-pass (unchanged from round 6/7)
// A-layout: per (mb = m>>7, kt = k>>5) block of 4096 floats, tiles of 128.
// B-layout: per (nb = n>>7, kt) block of 4096 floats, tiles of 128.
// ---------------------------------------------------------------------------
__global__ void __launch_bounds__(256) permA_kernel(
    const float* __restrict__ in, float* __restrict__ out, int K)
{
    __shared__ float t[128][33];
    const int kt = blockIdx.x, mb = blockIdx.y;
    const int tid = threadIdx.x;
    const int nkt = K >> 5;
    const float* src = in + (size_t)mb * 128 * K + kt * 32;
    #pragma unroll
    for (int i = 0; i < 4; ++i) {
        const int row = (tid >> 3) + i * 32;
        const int c4  = (tid & 7) * 4;
        float4 v = *(const float4*)(src + (size_t)row * K + c4);
        t[row][c4] = v.x; t[row][c4+1] = v.y; t[row][c4+2] = v.z; t[row][c4+3] = v.w;
    }
    __syncthreads();
    float* dst = out + (size_t)(mb * nkt + kt) * 4096;
    #pragma unroll
    for (int i = 0; i < 4; ++i) {
        const int f = tid + i * 256;
        const int tile = f >> 5, lane = f & 31;
        const int mtile = tile >> 2, ks = tile & 3;
        const int qr = lane >> 2, qc = lane & 3;
        const int m0 = mtile * 16 + qr, k0 = ks * 8 + qc;
        uint4 u;
        u.x = tf32_rne(t[m0][k0]);
        u.y = tf32_rne(t[m0 + 8][k0]);
        u.z = tf32_rne(t[m0][k0 + 4]);
        u.w = tf32_rne(t[m0 + 8][k0 + 4]);
        *(uint4*)(dst + f * 4) = u;
    }
}

__global__ void __launch_bounds__(256) permB_kernel(
    const float* __restrict__ in, float* __restrict__ out, int K)
{
    __shared__ float t[128][33];
    const int kt = blockIdx.x, nb = blockIdx.y;
    const int tid = threadIdx.x;
    const int nkt = K >> 5;
    const float* src = in + (size_t)nb * 128 * K + kt * 32;
    #pragma unroll
    for (int i = 0; i < 4; ++i) {
        const int row = (tid >> 3) + i * 32;
        const int c4  = (tid & 7) * 4;
        float4 v = *(const float4*)(src + (size_t)row * K + c4);
        t[row][c4] = v.x; t[row][c4+1] = v.y; t[row][c4+2] = v.z; t[row][c4+3] = v.w;
    }
    __syncthreads();
    float* dst = out + (size_t)(nb * nkt + kt) * 4096;
    #pragma unroll
    for (int i = 0; i < 4; ++i) {
        const int f = tid + i * 256;
        const int tile = f >> 5, lane = f & 31;
        const int ntile = tile >> 1, kp = tile & 1;
        const int qr = lane >> 2, qc = lane & 3;
        const int n0 = ntile * 8 + qr, k0 = kp * 16 + qc;
        uint4 u;
        u.x = tf32_rne(t[n0][k0]);
        u.y = tf32_rne(t[n0][k0 + 4]);
        u.z = tf32_rne(t[n0][k0 + 8]);
        u.w = tf32_rne(t[n0][k0 + 12]);
        *(uint4*)(dst + f * 4) = u;
    }
}

// ---------------------------------------------------------------------------
// tf32 mma GEMM, 256x128 CTA tile (2 A-blocks + 1 B-block per k-tile stage),
// 8 warps in 4x2, warp tile 64x64. 3-stage cp.async, fragment-major inputs.
// Per-output smem traffic 33% lower than the 128x128 / 2x4 arrangement.
// MODE 0: fp32 store. MODE 1: tf32 scatter into g_q/g_k/g_v (Q scaled 1/8).
// ---------------------------------------------------------------------------
#define NSTAGE 3
#define STG_FLOATS 12288
#define GEMM_SMEM (NSTAGE * STG_FLOATS * (int)sizeof(float))   // 147456

__device__ __forceinline__ void g_issue(
    const float* __restrict__ A0, const float* __restrict__ A1,
    const float* __restrict__ Wb, int kt, uint32_t smem_base, int s, int tid)
{
    const uint32_t dst = smem_base + (s * STG_FLOATS + tid * 16) * 4;
    const float* a0 = A0 + (size_t)kt * 4096 + tid * 16;
    const float* a1 = A1 + (size_t)kt * 4096 + tid * 16;
    const float* b  = Wb + (size_t)kt * 4096 + tid * 16;
    #pragma unroll
    for (int j = 0; j < 4; ++j) {
        cp_async16(dst + j * 16,            a0 + j * 4);
        cp_async16(dst + 4096 * 4 + j * 16, a1 + j * 4);
        cp_async16(dst + 8192 * 4 + j * 16, b  + j * 4);
    }
    cp_commit();
}

template<int MODE>
__global__ void __launch_bounds__(256, 1) gemm_mma_kernel(
    const float* __restrict__ A, const float* __restrict__ W,
    const float* __restrict__ bias, float* __restrict__ out,
    int N, int K)
{
    extern __shared__ float sm[];
    const int tid  = threadIdx.x;
    const int lane = tid & 31;
    const int wid  = tid >> 5;
    const int wm   = wid & 3;        // 4 M strips of 64
    const int wn   = wid >> 2;       // 2 N strips of 64
    const int qr   = lane >> 2;
    const int qc   = lane & 3;

    const int nkt = K >> 5;
    const int mb0 = blockIdx.y * 2, nb = blockIdx.x;
    const float* A0 = A + (size_t)mb0 * nkt * 4096;
    const float* A1 = A0 + (size_t)nkt * 4096;
    const float* Wb = W + (size_t)nb * nkt * 4096;

    const uint32_t smem_base = cvta_smem(sm);

    float acc[4][8][4];
    #pragma unroll
    for (int i = 0; i < 4; ++i)
        #pragma unroll
        for (int j = 0; j < 8; ++j)
            #pragma unroll
            for (int r = 0; r < 4; ++r) acc[i][j][r] = 0.f;

    #pragma unroll
    for (int s = 0; s < 2; ++s)
        g_issue(A0, A1, Wb, s, smem_base, s, tid);

    for (int kt = 0; kt < nkt; ++kt) {
        __syncthreads();
        if (kt + 2 < nkt) {
            g_issue(A0, A1, Wb, kt + 2, smem_base, (kt + 2) % NSTAGE, tid);
            cp_wait2();
        } else if (kt + 1 < nkt) {
            cp_wait1();
        } else {
            cp_wait0();
        }
        __syncthreads();

        const uint32_t* Sf = (const uint32_t*)(sm + (kt % NSTAGE) * STG_FLOATS);
        const uint32_t* Af = Sf + (wm >> 1) * 4096;   // warp's A half-block
        const uint32_t* Bf = Sf + 8192;
        const int mloc = (wm & 1) * 4;                // local mtile base in half-block

        uint32_t bq[8][4];
        #pragma unroll
        for (int ks = 0; ks < 4; ++ks) {
            uint32_t af[4][4];
            #pragma unroll
            for (int mt = 0; mt < 4; ++mt)
                *(uint4*)af[mt] = *(const uint4*)(Af + ((mloc + mt) * 4 + ks) * 128 + lane * 4);
            if ((ks & 1) == 0) {
                #pragma unroll
                for (int nt = 0; nt < 8; ++nt) {
                    const int ntile = wn * 8 + nt;
                    *(uint4*)bq[nt] = *(const uint4*)(Bf + (ntile * 2 + (ks >> 1)) * 128 + lane * 4);
                }
            }
            #pragma unroll
            for (int mt = 0; mt < 4; ++mt)
                #pragma unroll
                for (int nt = 0; nt < 8; ++nt) {
                    uint32_t bf2[2] = { bq[nt][(ks & 1) * 2], bq[nt][(ks & 1) * 2 + 1] };
                    mma_tf32(acc[mt][nt], af[mt], bf2);
                }
        }
    }

    const int rowBase = blockIdx.y * 256, colBase = nb * 128;
    #pragma unroll
    for (int nt = 0; nt < 8; ++nt) {
        const int n0 = colBase + wn * 64 + nt * 8 + qc * 2;
        const float b0 = bias[n0], b1 = bias[n0 + 1];
        #pragma unroll
        for (int mt = 0; mt < 4; ++mt) {
            const int m0 = rowBase + wm * 64 + mt * 16 + qr;
            float2 v0 = make_float2(acc[mt][nt][0] + b0, acc[mt][nt][1] + b1);
            float2 v1 = make_float2(acc[mt][nt][2] + b0, acc[mt][nt][3] + b1);
            if (MODE == 0) {
                *(float2*)(out + (size_t)m0 * N + n0)       = v0;
                *(float2*)(out + (size_t)(m0 + 8) * N + n0) = v1;
            } else {
                const int sector = n0 >> 10;          // 0=Q 1=K 2=V
                const int c  = n0 & 1023;
                const int hh = c >> 6, dd = c & 63;
                float* dst = (sector == 0) ? g_q : (sector == 1) ? g_k : g_v;
                const float qs = (sector == 0) ? 0.125f : 1.0f;
                uint2 u0, u1;
                u0.x = tf32_rne(v0.x * qs); u0.y = tf32_rne(v0.y * qs);
                u1.x = tf32_rne(v1.x * qs); u1.y = tf32_rne(v1.y * qs);
                const int bb0 = m0 >> 11, tt0 = m0 & 2047;
                *(uint2*)(dst + ((((size_t)bb0 * H_ + hh) * T_) + tt0) * D_ + dd) = u0;
                const int m1 = m0 + 8;
                const int bb1 = m1 >> 11, tt1 = m1 & 2047;
                *(uint2*)(dst + ((((size_t)bb1 * H_ + hh) * T_) + tt1) * D_ + dd) = u1;
            }
        }
    }
}

// ---------------------------------------------------------------------------
// Tensor-core flash attention (round 7, proven): tf32 mma, double-buffered
// K/V, Q in registers, 2 CTAs/SM. Epilogue writes fragment-major y.
// ---------------------------------------------------------------------------
#define QP 68
#define VP 72
#define KV_FLOATS (64*QP + 64*VP)
#define ATTN_SMEM ((128*QP + 2*KV_FLOATS) * (int)sizeof(float))  // 106496

__global__ void __launch_bounds__(256, 2) attn_mma_kernel(float* __restrict__ Y)
{
    extern __shared__ float sm[];
    float* Ps = sm;                      // [128][QP]
    float* KV = Ps + 128*QP;

    const int qt  = gridDim.x - 1 - blockIdx.x;
    const int bh  = blockIdx.y;
    const int b   = bh >> 4, h = bh & 15;
    const int tid = threadIdx.x;
    const int lane = tid & 31;
    const int w    = tid >> 5;
    const int qr   = lane >> 2;
    const int qc   = lane & 3;

    const float* Qg = g_q + ((size_t)bh * T_ + qt * 128) * D_;
    const float* Kg = g_k + (size_t)bh * T_ * D_;
    const float* Vg = g_v + (size_t)bh * T_ * D_;

    const uint32_t kv_u = cvta_smem(KV);

    #pragma unroll
    for (int t = 0; t < 4; ++t) {
        const int slot = tid + t * 256;
        const int r  = slot >> 4;
        const int d0 = (slot & 15) << 2;
        cp_async16(kv_u + (r * QP + d0) * 4, Kg + r * 64 + d0);
        cp_async16(kv_u + (64*QP + r * VP + d0) * 4, Vg + r * 64 + d0);
    }
    cp_commit();

    #pragma unroll
    for (int t = 0; t < 8; ++t) {
        const int slot = tid + t * 256;
        const int r  = slot >> 4;
        const int d0 = (slot & 15) << 2;
        *(float4*)(Ps + r * QP + d0) = *(const float4*)(Qg + r * 64 + d0);
    }
    __syncthreads();
    uint32_t qf[8][4];
    {
        const uint32_t* qb = (const uint32_t*)(Ps + (w*16 + qr) * QP);
        #pragma unroll
        for (int kc = 0; kc < 8; ++kc) {
            qf[kc][0] = qb[kc*8 + qc];
            qf[kc][1] = qb[8*QP + kc*8 + qc];
            qf[kc][2] = qb[kc*8 + qc + 4];
            qf[kc][3] = qb[8*QP + kc*8 + qc + 4];
        }
    }

    float m0 = NEG_BIG, m1 = NEG_BIG, l0 = 0.f, l1 = 0.f;
    float oacc[8][4];
    #pragma unroll
    for (int nt = 0; nt < 8; ++nt)
        #pragma unroll
        for (int r = 0; r < 4; ++r) oacc[nt][r] = 0.f;

    const int row0 = w * 16 + qr;
    const int jmax = 2 * qt + 1;

    for (int j = 0; j <= jmax; ++j) {
        __syncthreads();

        if (j + 1 <= jmax) {
            const uint32_t stg = kv_u + ((j + 1) & 1) * KV_FLOATS * 4;
            const float* Kgt = Kg + (size_t)(j + 1) * 64 * 64;
            const float* Vgt = Vg + (size_t)(j + 1) * 64 * 64;
            #pragma unroll
            for (int t = 0; t < 4; ++t) {
                const int slot = tid + t * 256;
                const int r  = slot >> 4;
                const int d0 = (slot & 15) << 2;
                cp_async16(stg + (r * QP + d0) * 4, Kgt + r * 64 + d0);
                cp_async16(stg + (64*QP + r * VP + d0) * 4, Vgt + r * 64 + d0);
            }
            cp_commit();
            cp_wait1();
        } else {
            cp_wait0();
        }
        __syncthreads();

        const float* Ks = KV + (j & 1) * KV_FLOATS;
        const float* Vs = Ks + 64*QP;

        int ntmax = 8;
        if (j == 2 * qt) {
            ntmax = 2 * w + 2; if (ntmax > 8) ntmax = 8;
        } else if (j == 2 * qt + 1) {
            ntmax = 2 * w - 6; if (ntmax < 0) ntmax = 0;
        }

        if (ntmax > 0) {
            float sacc[8][4];
            #pragma unroll
            for (int nt = 0; nt < 8; ++nt)
                #pragma unroll
                for (int r = 0; r < 4; ++r) sacc[nt][r] = 0.f;

            #pragma unroll
            for (int kc = 0; kc < 8; ++kc) {
                #pragma unroll
                for (int nt = 0; nt < 8; ++nt) {
                    if (nt < ntmax) {
                        uint32_t bf[2];
                        const uint32_t* kb = (const uint32_t*)(Ks + (nt*8 + qr) * QP + kc*8 + qc);
                        bf[0] = kb[0];
                        bf[1] = kb[4];
                        mma_tf32(sacc[nt], qf[kc], bf);
                    }
                }
            }

            if (j >= 2 * qt) {
                const int rel = (j - 2 * qt) * 64;
                #pragma unroll
                for (int nt = 0; nt < 8; ++nt) {
                    if (nt < ntmax) {
                        const int col = rel + nt * 8 + qc * 2;
                        if (col     > row0)     sacc[nt][0] = NEG_BIG;
                        if (col + 1 > row0)     sacc[nt][1] = NEG_BIG;
                        if (col     > row0 + 8) sacc[nt][2] = NEG_BIG;
                        if (col + 1 > row0 + 8) sacc[nt][3] = NEG_BIG;
                    }
                }
            }

            float rmax0 = NEG_BIG, rmax1 = NEG_BIG;
            #pragma unroll
            for (int nt = 0; nt < 8; ++nt) {
                if (nt < ntmax) {
                    rmax0 = fmaxf(rmax0, fmaxf(sacc[nt][0], sacc[nt][1]));
                    rmax1 = fmaxf(rmax1, fmaxf(sacc[nt][2], sacc[nt][3]));
                }
            }
            rmax0 = fmaxf(rmax0, __shfl_xor_sync(0xffffffffu, rmax0, 1));
            rmax0 = fmaxf(rmax0, __shfl_xor_sync(0xffffffffu, rmax0, 2));
            rmax1 = fmaxf(rmax1, __shfl_xor_sync(0xffffffffu, rmax1, 1));
            rmax1 = fmaxf(rmax1, __shfl_xor_sync(0xffffffffu, rmax1, 2));

            const float mn0 = fmaxf(m0, rmax0);
            const float mn1 = fmaxf(m1, rmax1);
            const float al0 = __expf(m0 - mn0);
            const float al1 = __expf(m1 - mn1);

            float rs0 = 0.f, rs1 = 0.f;
            #pragma unroll
            for (int nt = 0; nt < 8; ++nt) {
                if (nt < ntmax) {
                    const float p00 = __expf(sacc[nt][0] - mn0);
                    const float p01 = __expf(sacc[nt][1] - mn0);
                    const float p10 = __expf(sacc[nt][2] - mn1);
                    const float p11 = __expf(sacc[nt][3] - mn1);
                    rs0 += p00 + p01;
                    rs1 += p10 + p11;
                    uint2 u0; u0.x = tf32_rne(p00); u0.y = tf32_rne(p01);
                    uint2 u1; u1.x = tf32_rne(p10); u1.y = tf32_rne(p11);
                    *(uint2*)(Ps + row0 * QP + nt*8 + qc*2)       = u0;
                    *(uint2*)(Ps + (row0 + 8) * QP + nt*8 + qc*2) = u1;
                }
            }
            rs0 += __shfl_xor_sync(0xffffffffu, rs0, 1);
            rs0 += __shfl_xor_sync(0xffffffffu, rs0, 2);
            rs1 += __shfl_xor_sync(0xffffffffu, rs1, 1);
            rs1 += __shfl_xor_sync(0xffffffffu, rs1, 2);

            l0 = l0 * al0 + rs0;
            l1 = l1 * al1 + rs1;
            m0 = mn0;
            m1 = mn1;

            #pragma unroll
            for (int nt = 0; nt < 8; ++nt) {
                oacc[nt][0] *= al0; oacc[nt][1] *= al0;
                oacc[nt][2] *= al1; oacc[nt][3] *= al1;
            }

            __syncwarp();

            #pragma unroll
            for (int kc = 0; kc < 8; ++kc) {
                if (kc < ntmax) {
                    uint32_t a[4];
                    const uint32_t* pb = (const uint32_t*)(Ps + (w*16 + qr) * QP + kc*8 + qc);
                    a[0] = pb[0];
                    a[1] = pb[8 * QP];
                    a[2] = pb[4];
                    a[3] = pb[8 * QP + 4];
                    #pragma unroll
                    for (int nt = 0; nt < 8; ++nt) {
                        uint32_t bf[2];
                        const uint32_t* vb = (const uint32_t*)(Vs + (kc*8 + qc) * VP + nt*8 + qr);
                        bf[0] = vb[0];
                        bf[1] = vb[4 * VP];
                        mma_tf32(oacc[nt], a, bf);
                    }
                }
            }
        }
    }

    // Epilogue: normalize, tf32-round, scatter into fragment-major y
    const float inv0 = 1.0f / l0;
    const float inv1 = 1.0f / l1;
    const int lo = qr * 4 + ((qc * 2) & 3);
    const int hb = (qc >> 1) << 1;
    #pragma unroll
    for (int nt = 0; nt < 8; ++nt) {
        const int ktc = h * 2 + (nt >> 2);
        const int ks  = nt & 3;
        uint32_t* blk = (uint32_t*)(Y + ((size_t)((b * 16 + qt) * 32 + ktc)) * 4096
                                      + (w * 4 + ks) * 128);
        blk[lo * 4 + hb]           = tf32_rne(oacc[nt][0] * inv0);
        blk[(lo + 1) * 4 + hb]     = tf32_rne(oacc[nt][1] * inv0);
        blk[lo * 4 + hb + 1]       = tf32_rne(oacc[nt][2] * inv1);
        blk[(lo + 1) * 4 + hb + 1] = tf32_rne(oacc[nt][3] * inv1);
    }
}

// ---------------------------------------------------------------------------
extern "C" void kernel_launch(void* const* d_in, const int* in_sizes, int n_in,
                              void* d_out, int out_size)
{
    const float* x      = (const float*)d_in[0];
    const float* w_attn = (const float*)d_in[1];
    const float* b_attn = (const float*)d_in[2];
    const float* w_proj = (const float*)d_in[3];
    const float* b_proj = (const float*)d_in[4];
    float* out = (float*)d_out;

    float *yptr = nullptr, *xr = nullptr, *war = nullptr, *wpr = nullptr;
    cudaGetSymbolAddress((void**)&yptr, g_y);
    cudaGetSymbolAddress((void**)&xr,   g_xr);
    cudaGetSymbolAddress((void**)&war,  g_war);
    cudaGetSymbolAddress((void**)&wpr,  g_wpr);

    cudaFuncSetAttribute(gemm_mma_kernel<1>,
                         cudaFuncAttributeMaxDynamicSharedMemorySize, GEMM_SMEM);
    cudaFuncSetAttribute(gemm_mma_kernel<0>,
                         cudaFuncAttributeMaxDynamicSharedMemorySize, GEMM_SMEM);
    cudaFuncSetAttribute(attn_mma_kernel,
                         cudaFuncAttributeMaxDynamicSharedMemorySize, ATTN_SMEM);

    // 0) Pre-pass: permute to fragment-major + tf32 round
    permA_kernel<<<dim3(32, 64), 256>>>(x,      xr,  C_DIM);
    permB_kernel<<<dim3(32, 24), 256>>>(w_attn, war, C_DIM);
    permB_kernel<<<dim3(32,  8), 256>>>(w_proj, wpr, C_DIM);

    // 1) QKV projection (256x128 tiles); epilogue rounds + scatters Q/K/V
    dim3 g1(QKV_N / 128, M_ROWS / 256);   // 24 x 32
    gemm_mma_kernel<1><<<g1, 256, GEMM_SMEM>>>(xr, war, b_attn, nullptr, QKV_N, C_DIM);

    // 2) Causal flash attention -> g_y (fragment-major, tf32)
    dim3 g2(T_ / 128, B_ * H_);           // 16 x 64
    attn_mma_kernel<<<g2, 256, ATTN_SMEM>>>(yptr);

    // 3) Output projection -> d_out (fp32)
    dim3 g3(C_DIM / 128, M_ROWS / 256);   // 8 x 32
    gemm_mma_kernel<0><<<g3, 256, GEMM_SMEM>>>(yptr, wpr, b_proj, out, C_DIM, C_DIM);
}

// round 10
// speedup vs baseline: 2.1312x; 2.1312x over previous
#include <cuda_runtime.h>
#include <cuda_fp16.h>
#include <cstdint>

// Problem constants
#define B_    4
#define T_    2048
#define C_DIM 1024
#define H_    16
#define D_    64
#define M_ROWS (B_*T_)      // 8192
#define QKV_N  (3*C_DIM)    // 3072
#define NEG_BIG (-3.0e38f)

// Scratch (device globals; fp16 payloads use half the space)
__device__ float g_q[4194304];    // half [B,H,T,D], Q pre-scaled by 1/8
__device__ float g_k[4194304];    // half [B,H,T,D]
__device__ float g_v[4194304];    // half [B,H,D,T]  (TRANSPOSED for PV B-frags)
__device__ float g_y[4194304];    // half, fragment-major A-layout
__device__ float g_xr[4194304];   // half, fragment-major A-layout
__device__ float g_war[1572864];  // half, fragment-major B-layout
__device__ float g_wpr[524288];   // half, fragment-major B-layout

// ---------------------------------------------------------------------------
// Helpers
// ---------------------------------------------------------------------------
__device__ __forceinline__ uint32_t cvta_smem(const void* p) {
    uint32_t a;
    asm("{ .reg .u64 t; cvta.to.shared.u64 t, %1; cvt.u32.u64 %0, t; }"
        : "=r"(a) : "l"(p));
    return a;
}
__device__ __forceinline__ void cp_async16(uint32_t dst, const void* src) {
    asm volatile("cp.async.cg.shared.global [%0], [%1], 16;" :: "r"(dst), "l"(src));
}
__device__ __forceinline__ void cp_commit() { asm volatile("cp.async.commit_group;"); }
__device__ __forceinline__ void cp_wait0()  { asm volatile("cp.async.wait_group 0;"); }
__device__ __forceinline__ void cp_wait1()  { asm volatile("cp.async.wait_group 1;"); }
__device__ __forceinline__ void cp_wait2()  { asm volatile("cp.async.wait_group 2;"); }

__device__ __forceinline__ uint32_t pack_h2(float a, float b) {
    __half2 h = __floats2half2_rn(a, b);
    return *reinterpret_cast<uint32_t*>(&h);
}
// fp16 mma m16n8k16, fp32 accumulate
__device__ __forceinline__ void mma_f16(float* d, const uint32_t* a, const uint32_t* b) {
    asm volatile(
        "mma.sync.aligned.m16n8k16.row.col.f32.f16.f16.f32 "
        "{%0,%1,%2,%3}, {%4,%5,%6,%7}, {%8,%9}, {%0,%1,%2,%3};"
        : "+f"(d[0]), "+f"(d[1]), "+f"(d[2]), "+f"(d[3])
        : "r"(a[0]), "r"(a[1]), "r"(a[2]), "r"(a[3]), "r"(b[0]), "r"(b[1]));
}

// ---------------------------------------------------------------------------
// Prepass: fp32 -> fp16 fragment-major.
// A-layout per (mb=m>>7, kt=k>>5) block: 2048 uint32; tile = mtile*2+kstep
// (mtile 0..7 of 16 rows, kstep 0..1 of 16 k). Per tile 128 u32: lane*4+reg:
//   reg0=(qr, 2qc..+1) reg1=(qr+8,..) reg2=(qr, 2qc+8..9) reg3=(qr+8,..)
// B-layout per (nb, kt) block: 2048 u32; tile = ntile (0..15 of 8 n). Per
// tile: lane*4+reg: reg = kstep*2 + koff8: (qr, kstep*16 + 2qc + koff*8)
// ---------------------------------------------------------------------------
__global__ void __launch_bounds__(256) permA_kernel(
    const float* __restrict__ in, uint32_t* __restrict__ out, int K)
{
    __shared__ float t[128][33];
    const int kt = blockIdx.x, mb = blockIdx.y;
    const int tid = threadIdx.x;
    const int nkt = K >> 5;
    const float* src = in + (size_t)mb * 128 * K + kt * 32;
    #pragma unroll
    for (int i = 0; i < 4; ++i) {
        const int row = (tid >> 3) + i * 32;
        const int c4  = (tid & 7) * 4;
        float4 v = *(const float4*)(src + (size_t)row * K + c4);
        t[row][c4] = v.x; t[row][c4+1] = v.y; t[row][c4+2] = v.z; t[row][c4+3] = v.w;
    }
    __syncthreads();
    uint32_t* dst = out + (size_t)(mb * nkt + kt) * 2048;
    #pragma unroll
    for (int i = 0; i < 8; ++i) {
        const int idx = tid + i * 256;
        const int tile = idx >> 7, lr = idx & 127;
        const int lane = lr >> 2, reg = lr & 3;
        const int mtile = tile >> 1, kstep = tile & 1;
        const int qr = lane >> 2, qc = lane & 3;
        const int m = mtile * 16 + qr + (reg & 1) * 8;
        const int kk = kstep * 16 + qc * 2 + (reg >> 1) * 8;
        dst[idx] = pack_h2(t[m][kk], t[m][kk + 1]);
    }
}

__global__ void __launch_bounds__(256) permB_kernel(
    const float* __restrict__ in, uint32_t* __restrict__ out, int K)
{
    __shared__ float t[128][33];
    const int kt = blockIdx.x, nb = blockIdx.y;
    const int tid = threadIdx.x;
    const int nkt = K >> 5;
    const float* src = in + (size_t)nb * 128 * K + kt * 32;
    #pragma unroll
    for (int i = 0; i < 4; ++i) {
        const int row = (tid >> 3) + i * 32;
        const int c4  = (tid & 7) * 4;
        float4 v = *(const float4*)(src + (size_t)row * K + c4);
        t[row][c4] = v.x; t[row][c4+1] = v.y; t[row][c4+2] = v.z; t[row][c4+3] = v.w;
    }
    __syncthreads();
    uint32_t* dst = out + (size_t)(nb * nkt + kt) * 2048;
    #pragma unroll
    for (int i = 0; i < 8; ++i) {
        const int idx = tid + i * 256;
        const int tile = idx >> 7, lr = idx & 127;
        const int lane = lr >> 2, reg = lr & 3;
        const int qr = lane >> 2, qc = lane & 3;
        const int n = tile * 8 + qr;
        const int kk = (reg >> 1) * 16 + qc * 2 + (reg & 1) * 8;
        dst[idx] = pack_h2(t[n][kk], t[n][kk + 1]);
    }
}

// ---------------------------------------------------------------------------
// fp16 mma GEMM: 128x128x32 CTA tile, 8 warps (2x4), warp 64x32, 3-stage
// cp.async. Stage = A 2048 + B 2048 uint32 = 16 KB -> 48 KB total, 2 CTAs/SM.
// MODE 0: fp32 store. MODE 1: fp16 Q/K row-major + V transposed.
// ---------------------------------------------------------------------------
#define NSTAGE 3
#define STG_U32 4096
#define GEMM_SMEM (NSTAGE * STG_U32 * 4)   // 49152

__device__ __forceinline__ void g_issue(
    const uint32_t* __restrict__ Ab, const uint32_t* __restrict__ Wb,
    int kt, uint32_t smem_base, int s, int tid)
{
    const uint32_t dst = smem_base + (s * STG_U32 + tid * 8) * 4;
    const uint32_t* a = Ab + (size_t)kt * 2048 + tid * 8;
    const uint32_t* b = Wb + (size_t)kt * 2048 + tid * 8;
    cp_async16(dst,                  a);
    cp_async16(dst + 16,             a + 4);
    cp_async16(dst + 2048 * 4,       b);
    cp_async16(dst + 2048 * 4 + 16,  b + 4);
    cp_commit();
}

template<int MODE>
__global__ void __launch_bounds__(256) gemm_f16_kernel(
    const uint32_t* __restrict__ A, const uint32_t* __restrict__ W,
    const float* __restrict__ bias, float* __restrict__ out,
    int N, int K)
{
    extern __shared__ float smf[];
    uint32_t* sm = (uint32_t*)smf;
    const int tid  = threadIdx.x;
    const int lane = tid & 31;
    const int wid  = tid >> 5;
    const int wm   = wid & 1;
    const int wn   = wid >> 1;
    const int qr   = lane >> 2;
    const int qc   = lane & 3;

    const int nkt = K >> 5;
    const int mb = blockIdx.y, nb = blockIdx.x;
    const uint32_t* Ab = A + (size_t)mb * nkt * 2048;
    const uint32_t* Wb = W + (size_t)nb * nkt * 2048;
    const uint32_t smem_base = cvta_smem(sm);

    float acc[4][4][4];
    #pragma unroll
    for (int i = 0; i < 4; ++i)
        #pragma unroll
        for (int j = 0; j < 4; ++j)
            #pragma unroll
            for (int r = 0; r < 4; ++r) acc[i][j][r] = 0.f;

    g_issue(Ab, Wb, 0, smem_base, 0, tid);
    g_issue(Ab, Wb, 1, smem_base, 1, tid);

    for (int kt = 0; kt < nkt; ++kt) {
        __syncthreads();
        if (kt + 2 < nkt) {
            g_issue(Ab, Wb, kt + 2, smem_base, (kt + 2) % NSTAGE, tid);
            cp_wait2();
        } else if (kt + 1 < nkt) {
            cp_wait1();
        } else {
            cp_wait0();
        }
        __syncthreads();

        const uint32_t* Af = sm + (kt % NSTAGE) * STG_U32;
        const uint32_t* Bf = Af + 2048;

        uint32_t bq[4][4];
        #pragma unroll
        for (int nt = 0; nt < 4; ++nt)
            *(uint4*)bq[nt] = *(const uint4*)(Bf + (wn * 4 + nt) * 128 + lane * 4);

        #pragma unroll
        for (int ks = 0; ks < 2; ++ks) {
            uint32_t af[4][4];
            #pragma unroll
            for (int mt = 0; mt < 4; ++mt)
                *(uint4*)af[mt] = *(const uint4*)(Af + ((wm * 4 + mt) * 2 + ks) * 128 + lane * 4);
            #pragma unroll
            for (int mt = 0; mt < 4; ++mt)
                #pragma unroll
                for (int nt = 0; nt < 4; ++nt) {
                    uint32_t b2[2] = { bq[nt][ks * 2], bq[nt][ks * 2 + 1] };
                    mma_f16(acc[mt][nt], af[mt], b2);
                }
        }
    }

    const int rowBase = mb * 128, colBase = nb * 128;
    #pragma unroll
    for (int nt = 0; nt < 4; ++nt) {
        const int n0 = colBase + wn * 32 + nt * 8 + qc * 2;
        const float b0 = bias[n0], b1 = bias[n0 + 1];
        #pragma unroll
        for (int mt = 0; mt < 4; ++mt) {
            const int m0 = rowBase + wm * 64 + mt * 16 + qr;
            float2 v0 = make_float2(acc[mt][nt][0] + b0, acc[mt][nt][1] + b1);
            float2 v1 = make_float2(acc[mt][nt][2] + b0, acc[mt][nt][3] + b1);
            if (MODE == 0) {
                *(float2*)(out + (size_t)m0 * N + n0)       = v0;
                *(float2*)(out + (size_t)(m0 + 8) * N + n0) = v1;
            } else {
                const int sector = n0 >> 10;          // 0=Q 1=K 2=V
                const int c  = n0 & 1023;
                const int hh = c >> 6, dd = c & 63;
                const int bb0 = m0 >> 11, tt0 = m0 & 2047;
                const int bh = bb0 * 16 + hh;          // m0,m0+8 share batch (m%2048)
                if (sector < 2) {
                    __half* dst = (sector == 0) ? (__half*)g_q : (__half*)g_k;
                    const float qs = (sector == 0) ? 0.125f : 1.0f;
                    uint32_t u0 = pack_h2(v0.x * qs, v0.y * qs);
                    uint32_t u1 = pack_h2(v1.x * qs, v1.y * qs);
                    *(uint32_t*)(dst + ((size_t)bh * 2048 + tt0) * 64 + dd)     = u0;
                    *(uint32_t*)(dst + ((size_t)bh * 2048 + tt0 + 8) * 64 + dd) = u1;
                } else {
                    __half* vt = (__half*)g_v;         // [B,H,D,T]
                    __half* p0 = vt + ((size_t)bh * 64 + dd) * 2048 + tt0;
                    __half* p1 = p0 + 2048;            // dd+1
                    p0[0] = __float2half_rn(v0.x);
                    p1[0] = __float2half_rn(v0.y);
                    p0[8] = __float2half_rn(v1.x);
                    p1[8] = __float2half_rn(v1.y);
                }
            }
        }
    }
}

// ---------------------------------------------------------------------------
// fp16 tensor-core flash attention. CTA = (b,h,128-q tile), 8 warps, Q in
// registers, double-buffered K/V (64-key tiles). Smem rows pitch 36 uint32
// (144 B): bank = 4*qr + qc, conflict-free. y written fragment-major fp16.
// ---------------------------------------------------------------------------
#define PP 36                               // uint32 pitch per 64-half row
#define PS_U32 (128 * PP)                   // 4608
#define KV_STG (64 * PP * 2)                // 4608 (K then V)
#define ATTN_SMEM ((PS_U32 + 2 * KV_STG) * 4)  // 55296

__global__ void __launch_bounds__(256, 2) attn_f16_kernel(uint32_t* __restrict__ Yu)
{
    extern __shared__ float smf[];
    uint32_t* Ps = (uint32_t*)smf;
    uint32_t* KV = Ps + PS_U32;

    const int qt  = gridDim.x - 1 - blockIdx.x;
    const int bh  = blockIdx.y;
    const int b   = bh >> 4, h = bh & 15;
    const int tid = threadIdx.x;
    const int lane = tid & 31;
    const int w    = tid >> 5;
    const int qr   = lane >> 2;
    const int qc   = lane & 3;

    const __half* Qg = (const __half*)g_q + ((size_t)bh * 2048 + qt * 128) * 64;
    const __half* Kg = (const __half*)g_k + (size_t)bh * 2048 * 64;
    const __half* Vt = (const __half*)g_v + (size_t)bh * 64 * 2048;

    const uint32_t kv_b = cvta_smem(KV);

    // Prologue: cp.async KV tile 0 into stage 0
    #pragma unroll
    for (int t = 0; t < 2; ++t) {
        const int slot = tid + t * 256;      // 0..511
        const int r = slot >> 3, c = slot & 7;
        cp_async16(kv_b + (r * PP + c * 4) * 4, Kg + r * 64 + c * 8);
        cp_async16(kv_b + (64 * PP + r * PP + c * 4) * 4, Vt + (size_t)r * 2048 + c * 8);
    }
    cp_commit();

    // Stage Q through Ps (plain loads), pick up A-fragments into registers
    #pragma unroll
    for (int t = 0; t < 4; ++t) {
        const int slot = tid + t * 256;      // 0..1023
        const int r = slot >> 3, c = slot & 7;
        *(uint4*)(Ps + r * PP + c * 4) = *(const uint4*)(Qg + r * 64 + c * 8);
    }
    __syncthreads();
    uint32_t qf[4][4];
    {
        const uint32_t* qb = Ps + (w * 16 + qr) * PP;
        #pragma unroll
        for (int ks = 0; ks < 4; ++ks) {
            qf[ks][0] = qb[ks * 8 + qc];
            qf[ks][1] = qb[8 * PP + ks * 8 + qc];
            qf[ks][2] = qb[ks * 8 + qc + 4];
            qf[ks][3] = qb[8 * PP + ks * 8 + qc + 4];
        }
    }

    float m0 = NEG_BIG, m1 = NEG_BIG, l0 = 0.f, l1 = 0.f;
    float oacc[8][4];
    #pragma unroll
    for (int nt = 0; nt < 8; ++nt)
        #pragma unroll
        for (int r = 0; r < 4; ++r) oacc[nt][r] = 0.f;

    const int row0 = w * 16 + qr;
    const int jmax = 2 * qt + 1;

    for (int j = 0; j <= jmax; ++j) {
        __syncthreads();

        if (j + 1 <= jmax) {
            const uint32_t stg = kv_b + ((j + 1) & 1) * KV_STG * 4;
            const __half* Kgt = Kg + (size_t)(j + 1) * 64 * 64;
            const __half* Vgt = Vt + (j + 1) * 64;
            #pragma unroll
            for (int t = 0; t < 2; ++t) {
                const int slot = tid + t * 256;
                const int r = slot >> 3, c = slot & 7;
                cp_async16(stg + (r * PP + c * 4) * 4, Kgt + r * 64 + c * 8);
                cp_async16(stg + (64 * PP + r * PP + c * 4) * 4, Vgt + (size_t)r * 2048 + c * 8);
            }
            cp_commit();
            cp_wait1();
        } else {
            cp_wait0();
        }
        __syncthreads();

        const uint32_t* Ks = KV + (j & 1) * KV_STG;
        const uint32_t* Vs = Ks + 64 * PP;

        int ntmax = 8;
        if (j == 2 * qt) {
            ntmax = 2 * w + 2; if (ntmax > 8) ntmax = 8;
        } else if (j == 2 * qt + 1) {
            ntmax = 2 * w - 6; if (ntmax < 0) ntmax = 0;
        }

        if (ntmax > 0) {
            // ---- S = Q K^T (fp16 mma, Q in registers) ----
            float sacc[8][4];
            #pragma unroll
            for (int nt = 0; nt < 8; ++nt)
                #pragma unroll
                for (int r = 0; r < 4; ++r) sacc[nt][r] = 0.f;

            #pragma unroll
            for (int ks = 0; ks < 4; ++ks) {
                #pragma unroll
                for (int nt = 0; nt < 8; ++nt) {
                    if (nt < ntmax) {
                        const uint32_t* kb = Ks + (nt * 8 + qr) * PP + ks * 8 + qc;
                        uint32_t bf[2] = { kb[0], kb[4] };
                        mma_f16(sacc[nt], qf[ks], bf);
                    }
                }
            }

            // ---- Causal mask (diagonal tiles only) ----
            if (j >= 2 * qt) {
                const int rel = (j - 2 * qt) * 64;
                #pragma unroll
                for (int nt = 0; nt < 8; ++nt) {
                    if (nt < ntmax) {
                        const int col = rel + nt * 8 + qc * 2;
                        if (col     > row0)     sacc[nt][0] = NEG_BIG;
                        if (col + 1 > row0)     sacc[nt][1] = NEG_BIG;
                        if (col     > row0 + 8) sacc[nt][2] = NEG_BIG;
                        if (col + 1 > row0 + 8) sacc[nt][3] = NEG_BIG;
                    }
                }
            }

            // ---- Online softmax ----
            float rmax0 = NEG_BIG, rmax1 = NEG_BIG;
            #pragma unroll
            for (int nt = 0; nt < 8; ++nt) {
                if (nt < ntmax) {
                    rmax0 = fmaxf(rmax0, fmaxf(sacc[nt][0], sacc[nt][1]));
                    rmax1 = fmaxf(rmax1, fmaxf(sacc[nt][2], sacc[nt][3]));
                }
            }
            rmax0 = fmaxf(rmax0, __shfl_xor_sync(0xffffffffu, rmax0, 1));
            rmax0 = fmaxf(rmax0, __shfl_xor_sync(0xffffffffu, rmax0, 2));
            rmax1 = fmaxf(rmax1, __shfl_xor_sync(0xffffffffu, rmax1, 1));
            rmax1 = fmaxf(rmax1, __shfl_xor_sync(0xffffffffu, rmax1, 2));

            const float mn0 = fmaxf(m0, rmax0);
            const float mn1 = fmaxf(m1, rmax1);
            const float al0 = __expf(m0 - mn0);
            const float al1 = __expf(m1 - mn1);

            float rs0 = 0.f, rs1 = 0.f;
            #pragma unroll
            for (int nt = 0; nt < 8; ++nt) {
                if (nt < ntmax) {
                    const float p00 = __expf(sacc[nt][0] - mn0);
                    const float p01 = __expf(sacc[nt][1] - mn0);
                    const float p10 = __expf(sacc[nt][2] - mn1);
                    const float p11 = __expf(sacc[nt][3] - mn1);
                    rs0 += p00 + p01;
                    rs1 += p10 + p11;
                    Ps[row0 * PP + nt * 4 + qc]       = pack_h2(p00, p01);
                    Ps[(row0 + 8) * PP + nt * 4 + qc] = pack_h2(p10, p11);
                }
            }
            rs0 += __shfl_xor_sync(0xffffffffu, rs0, 1);
            rs0 += __shfl_xor_sync(0xffffffffu, rs0, 2);
            rs1 += __shfl_xor_sync(0xffffffffu, rs1, 1);
            rs1 += __shfl_xor_sync(0xffffffffu, rs1, 2);

            l0 = l0 * al0 + rs0;
            l1 = l1 * al1 + rs1;
            m0 = mn0;
            m1 = mn1;

            #pragma unroll
            for (int nt = 0; nt < 8; ++nt) {
                oacc[nt][0] *= al0; oacc[nt][1] *= al0;
                oacc[nt][2] *= al1; oacc[nt][3] *= al1;
            }

            __syncwarp();   // Ps stores visible warp-wide before PV A-frag loads

            // ---- O += P V (V transposed: rows = d) ----
            const int kmax = ntmax >> 1;     // ntmax is always even
            #pragma unroll
            for (int ks = 0; ks < 4; ++ks) {
                if (ks < kmax) {
                    const uint32_t* pb = Ps + (w * 16 + qr) * PP;
                    uint32_t a[4];
                    a[0] = pb[ks * 8 + qc];
                    a[1] = pb[8 * PP + ks * 8 + qc];
                    a[2] = pb[ks * 8 + qc + 4];
                    a[3] = pb[8 * PP + ks * 8 + qc + 4];
                    #pragma unroll
                    for (int nt = 0; nt < 8; ++nt) {
                        const uint32_t* vb = Vs + (nt * 8 + qr) * PP + ks * 8 + qc;
                        uint32_t bf[2] = { vb[0], vb[4] };
                        mma_f16(oacc[nt], a, bf);
                    }
                }
            }
        }
    }

    // Epilogue: normalize, pack fp16, scatter into fragment-major y.
    // m-block mb = b*16+qt, mtile = w; col c = h*64 + nt*8 + 2qc:
    // ktile = h*2 + (nt>>2), kstep = (nt>>1)&1, regbase = (nt&1)*2.
    const float inv0 = 1.0f / l0;
    const float inv1 = 1.0f / l1;
    const int mb = b * 16 + qt;
    #pragma unroll
    for (int nt = 0; nt < 8; ++nt) {
        const int ktc = h * 2 + (nt >> 2);
        const int kstep = (nt >> 1) & 1;
        const int rb = (nt & 1) * 2;
        uint32_t* blk = Yu + ((size_t)(mb * 32 + ktc) * 16 + (w * 2 + kstep)) * 128 + lane * 4;
        blk[rb]     = pack_h2(oacc[nt][0] * inv0, oacc[nt][1] * inv0);
        blk[rb + 1] = pack_h2(oacc[nt][2] * inv1, oacc[nt][3] * inv1);
    }
}

// ---------------------------------------------------------------------------
extern "C" void kernel_launch(void* const* d_in, const int* in_sizes, int n_in,
                              void* d_out, int out_size)
{
    const float* x      = (const float*)d_in[0];
    const float* w_attn = (const float*)d_in[1];
    const float* b_attn = (const float*)d_in[2];
    const float* w_proj = (const float*)d_in[3];
    const float* b_proj = (const float*)d_in[4];
    float* out = (float*)d_out;

    void *yv, *xv, *wav, *wpv;
    cudaGetSymbolAddress(&yv,  g_y);
    cudaGetSymbolAddress(&xv,  g_xr);
    cudaGetSymbolAddress(&wav, g_war);
    cudaGetSymbolAddress(&wpv, g_wpr);
    uint32_t* yu  = (uint32_t*)yv;
    uint32_t* xr  = (uint32_t*)xv;
    uint32_t* war = (uint32_t*)wav;
    uint32_t* wpr = (uint32_t*)wpv;

    cudaFuncSetAttribute(gemm_f16_kernel<1>,
                         cudaFuncAttributeMaxDynamicSharedMemorySize, GEMM_SMEM);
    cudaFuncSetAttribute(gemm_f16_kernel<0>,
                         cudaFuncAttributeMaxDynamicSharedMemorySize, GEMM_SMEM);
    cudaFuncSetAttribute(attn_f16_kernel,
                         cudaFuncAttributeMaxDynamicSharedMemorySize, ATTN_SMEM);

    // 0) Prepass: permute + fp16-round
    permA_kernel<<<dim3(32, 64), 256>>>(x,      xr,  C_DIM);
    permB_kernel<<<dim3(32, 24), 256>>>(w_attn, war, C_DIM);
    permB_kernel<<<dim3(32,  8), 256>>>(w_proj, wpr, C_DIM);

    // 1) QKV projection (fp16 mma); epilogue emits fp16 Q(scaled)/K + V^T
    dim3 g1(QKV_N / 128, M_ROWS / 128);   // 24 x 64
    gemm_f16_kernel<1><<<g1, 256, GEMM_SMEM>>>(xr, war, b_attn, nullptr, QKV_N, C_DIM);

    // 2) Causal flash attention (fp16 mma) -> y fragment-major fp16
    dim3 g2(T_ / 128, B_ * H_);           // 16 x 64
    attn_f16_kernel<<<g2, 256, ATTN_SMEM>>>(yu);

    // 3) Output projection (fp16 mma) -> d_out fp32
    dim3 g3(C_DIM / 128, M_ROWS / 128);   // 8 x 64
    gemm_f16_kernel<0><<<g3, 256, GEMM_SMEM>>>(yu, wpr, b_proj, out, C_DIM, C_DIM);
}

// round 11
// speedup vs baseline: 2.1418x; 1.0050x over previous
#include <cuda_runtime.h>
#include <cuda_fp16.h>
#include <cstdint>

// Problem constants
#define B_    4
#define T_    2048
#define C_DIM 1024
#define H_    16
#define D_    64
#define M_ROWS (B_*T_)      // 8192
#define QKV_N  (3*C_DIM)    // 3072
#define NEG_BIG (-3.0e38f)

// Scratch (device globals, fp16 payloads)
// g_q: A-frag-major per (bh, qblock, kt):   ((bh*16+qb)*2+kt)*2048 u32
// g_k: B-frag-major per (bh, keyblock, kt): (bh*32+kb*2+kt)*2048 u32  (n=key,k=d)
// g_v: B-frag-major per (bh, key32, dtile): bh*65536 + (k32*8+ntile)*128 u32 (n=d,k=key)
__device__ float g_q[4194304];
__device__ float g_k[4194304];
__device__ float g_v[4194304];
__device__ float g_y[4194304];    // half, fragment-major A-layout
__device__ float g_xr[4194304];   // half, fragment-major A-layout
__device__ float g_war[1572864];  // half, fragment-major B-layout
__device__ float g_wpr[524288];   // half, fragment-major B-layout

// ---------------------------------------------------------------------------
// Helpers
// ---------------------------------------------------------------------------
__device__ __forceinline__ uint32_t cvta_smem(const void* p) {
    uint32_t a;
    asm("{ .reg .u64 t; cvta.to.shared.u64 t, %1; cvt.u32.u64 %0, t; }"
        : "=r"(a) : "l"(p));
    return a;
}
__device__ __forceinline__ void cp_async16(uint32_t dst, const void* src) {
    asm volatile("cp.async.cg.shared.global [%0], [%1], 16;" :: "r"(dst), "l"(src));
}
__device__ __forceinline__ void cp_commit() { asm volatile("cp.async.commit_group;"); }
__device__ __forceinline__ void cp_wait0()  { asm volatile("cp.async.wait_group 0;"); }
__device__ __forceinline__ void cp_wait1()  { asm volatile("cp.async.wait_group 1;"); }
__device__ __forceinline__ void cp_wait2()  { asm volatile("cp.async.wait_group 2;"); }

__device__ __forceinline__ uint32_t pack_h2(float a, float b) {
    __half2 h = __floats2half2_rn(a, b);
    return *reinterpret_cast<uint32_t*>(&h);
}
__device__ __forceinline__ void mma_f16(float* d, const uint32_t* a, const uint32_t* b) {
    asm volatile(
        "mma.sync.aligned.m16n8k16.row.col.f32.f16.f16.f32 "
        "{%0,%1,%2,%3}, {%4,%5,%6,%7}, {%8,%9}, {%0,%1,%2,%3};"
        : "+f"(d[0]), "+f"(d[1]), "+f"(d[2]), "+f"(d[3])
        : "r"(a[0]), "r"(a[1]), "r"(a[2]), "r"(a[3]), "r"(b[0]), "r"(b[1]));
}

// ---------------------------------------------------------------------------
// Prepass: fp32 -> fp16 fragment-major (unchanged from round 10)
// ---------------------------------------------------------------------------
__global__ void __launch_bounds__(256) permA_kernel(
    const float* __restrict__ in, uint32_t* __restrict__ out, int K)
{
    __shared__ float t[128][33];
    const int kt = blockIdx.x, mb = blockIdx.y;
    const int tid = threadIdx.x;
    const int nkt = K >> 5;
    const float* src = in + (size_t)mb * 128 * K + kt * 32;
    #pragma unroll
    for (int i = 0; i < 4; ++i) {
        const int row = (tid >> 3) + i * 32;
        const int c4  = (tid & 7) * 4;
        float4 v = *(const float4*)(src + (size_t)row * K + c4);
        t[row][c4] = v.x; t[row][c4+1] = v.y; t[row][c4+2] = v.z; t[row][c4+3] = v.w;
    }
    __syncthreads();
    uint32_t* dst = out + (size_t)(mb * nkt + kt) * 2048;
    #pragma unroll
    for (int i = 0; i < 8; ++i) {
        const int idx = tid + i * 256;
        const int tile = idx >> 7, lr = idx & 127;
        const int lane = lr >> 2, reg = lr & 3;
        const int mtile = tile >> 1, kstep = tile & 1;
        const int qr = lane >> 2, qc = lane & 3;
        const int m = mtile * 16 + qr + (reg & 1) * 8;
        const int kk = kstep * 16 + qc * 2 + (reg >> 1) * 8;
        dst[idx] = pack_h2(t[m][kk], t[m][kk + 1]);
    }
}

__global__ void __launch_bounds__(256) permB_kernel(
    const float* __restrict__ in, uint32_t* __restrict__ out, int K)
{
    __shared__ float t[128][33];
    const int kt = blockIdx.x, nb = blockIdx.y;
    const int tid = threadIdx.x;
    const int nkt = K >> 5;
    const float* src = in + (size_t)nb * 128 * K + kt * 32;
    #pragma unroll
    for (int i = 0; i < 4; ++i) {
        const int row = (tid >> 3) + i * 32;
        const int c4  = (tid & 7) * 4;
        float4 v = *(const float4*)(src + (size_t)row * K + c4);
        t[row][c4] = v.x; t[row][c4+1] = v.y; t[row][c4+2] = v.z; t[row][c4+3] = v.w;
    }
    __syncthreads();
    uint32_t* dst = out + (size_t)(nb * nkt + kt) * 2048;
    #pragma unroll
    for (int i = 0; i < 8; ++i) {
        const int idx = tid + i * 256;
        const int tile = idx >> 7, lr = idx & 127;
        const int lane = lr >> 2, reg = lr & 3;
        const int qr = lane >> 2, qc = lane & 3;
        const int n = tile * 8 + qr;
        const int kk = (reg >> 1) * 16 + qc * 2 + (reg & 1) * 8;
        dst[idx] = pack_h2(t[n][kk], t[n][kk + 1]);
    }
}

// ---------------------------------------------------------------------------
// fp16 mma GEMM: 128x128x32 tile, 8 warps (2x4), 4-stage cp.async,
// SINGLE barrier per ktile. MODE 0: fp32 store. MODE 1: frag-major Q/K/V.
// ---------------------------------------------------------------------------
#define NSTAGE 4
#define STG_U32 4096
#define GEMM_SMEM (NSTAGE * STG_U32 * 4)   // 65536

__device__ __forceinline__ void g_issue(
    const uint32_t* __restrict__ Ab, const uint32_t* __restrict__ Wb,
    int kt, uint32_t smem_base, int s, int tid)
{
    const uint32_t dst = smem_base + (s * STG_U32 + tid * 8) * 4;
    const uint32_t* a = Ab + (size_t)kt * 2048 + tid * 8;
    const uint32_t* b = Wb + (size_t)kt * 2048 + tid * 8;
    cp_async16(dst,                  a);
    cp_async16(dst + 16,             a + 4);
    cp_async16(dst + 2048 * 4,       b);
    cp_async16(dst + 2048 * 4 + 16,  b + 4);
    cp_commit();
}

template<int MODE>
__global__ void __launch_bounds__(256) gemm_f16_kernel(
    const uint32_t* __restrict__ A, const uint32_t* __restrict__ W,
    const float* __restrict__ bias, float* __restrict__ out,
    int N, int K)
{
    extern __shared__ float smf[];
    uint32_t* sm = (uint32_t*)smf;
    const int tid  = threadIdx.x;
    const int lane = tid & 31;
    const int wid  = tid >> 5;
    const int wm   = wid & 1;
    const int wn   = wid >> 1;
    const int qr   = lane >> 2;
    const int qc   = lane & 3;

    const int nkt = K >> 5;
    const int mb = blockIdx.y, nb = blockIdx.x;
    const uint32_t* Ab = A + (size_t)mb * nkt * 2048;
    const uint32_t* Wb = W + (size_t)nb * nkt * 2048;
    const uint32_t smem_base = cvta_smem(sm);

    float acc[4][4][4];
    #pragma unroll
    for (int i = 0; i < 4; ++i)
        #pragma unroll
        for (int j = 0; j < 4; ++j)
            #pragma unroll
            for (int r = 0; r < 4; ++r) acc[i][j][r] = 0.f;

    g_issue(Ab, Wb, 0, smem_base, 0, tid);
    g_issue(Ab, Wb, 1, smem_base, 1, tid);
    g_issue(Ab, Wb, 2, smem_base, 2, tid);

    for (int kt = 0; kt < nkt; ++kt) {
        if (kt + 2 < nkt) cp_wait2(); else if (kt + 1 < nkt) cp_wait1(); else cp_wait0();
        __syncthreads();   // single barrier: all warps done with stage (kt-1)%4
        if (kt + 3 < nkt)
            g_issue(Ab, Wb, kt + 3, smem_base, (kt + 3) % NSTAGE, tid);

        const uint32_t* Af = sm + (kt % NSTAGE) * STG_U32;
        const uint32_t* Bf = Af + 2048;

        uint32_t bq[4][4];
        #pragma unroll
        for (int nt = 0; nt < 4; ++nt)
            *(uint4*)bq[nt] = *(const uint4*)(Bf + (wn * 4 + nt) * 128 + lane * 4);

        #pragma unroll
        for (int ks = 0; ks < 2; ++ks) {
            uint32_t af[4][4];
            #pragma unroll
            for (int mt = 0; mt < 4; ++mt)
                *(uint4*)af[mt] = *(const uint4*)(Af + ((wm * 4 + mt) * 2 + ks) * 128 + lane * 4);
            #pragma unroll
            for (int mt = 0; mt < 4; ++mt)
                #pragma unroll
                for (int nt = 0; nt < 4; ++nt) {
                    uint32_t b2[2] = { bq[nt][ks * 2], bq[nt][ks * 2 + 1] };
                    mma_f16(acc[mt][nt], af[mt], b2);
                }
        }
    }

    const int rowBase = mb * 128, colBase = nb * 128;
    uint32_t* Qu = (uint32_t*)g_q;
    uint32_t* Ku = (uint32_t*)g_k;
    __half*   Vh = (__half*)g_v;
    #pragma unroll
    for (int nt = 0; nt < 4; ++nt) {
        const int n0 = colBase + wn * 32 + nt * 8 + qc * 2;
        const float b0 = bias[n0], b1 = bias[n0 + 1];
        #pragma unroll
        for (int mt = 0; mt < 4; ++mt) {
            const int m0 = rowBase + wm * 64 + mt * 16 + qr;
            float2 v0 = make_float2(acc[mt][nt][0] + b0, acc[mt][nt][1] + b1);
            float2 v1 = make_float2(acc[mt][nt][2] + b0, acc[mt][nt][3] + b1);
            if (MODE == 0) {
                *(float2*)(out + (size_t)m0 * N + n0)       = v0;
                *(float2*)(out + (size_t)(m0 + 8) * N + n0) = v1;
            } else {
                const int sector = n0 >> 10;          // 0=Q 1=K 2=V
                const int c  = n0 & 1023;
                const int hh = c >> 6, dd = c & 63;
                const int tt = m0 & 2047;
                const int bh = (m0 >> 11) * 16 + hh;
                const int d5 = dd & 31;
                if (sector == 0) {
                    // A-frag-major Q, pre-scaled by 1/8
                    const size_t base = ((size_t)(bh * 16 + (tt >> 7)) * 2 + (dd >> 5)) * 2048;
                    const int tile = ((tt >> 4) & 7) * 2 + ((d5 >> 4) & 1);
                    const int ln   = (tt & 7) * 4 + ((d5 >> 1) & 3);
                    const int reg0 = ((d5 >> 3) & 1) * 2;
                    uint2 u;
                    u.x = pack_h2(v0.x * 0.125f, v0.y * 0.125f);
                    u.y = pack_h2(v1.x * 0.125f, v1.y * 0.125f);
                    *(uint2*)(Qu + base + tile * 128 + ln * 4 + reg0) = u;
                } else if (sector == 1) {
                    // B-frag-major K (n=key, k=d)
                    const size_t base = ((size_t)bh * 32 + (tt >> 7) * 2 + (dd >> 5)) * 2048;
                    const int tile = (tt >> 3) & 15;
                    const int ln   = (tt & 7) * 4 + ((d5 >> 1) & 3);
                    const int reg  = ((d5 >> 4) & 1) * 2 + ((d5 >> 3) & 1);
                    Ku[base + tile * 128 + ln * 4 + reg]       = pack_h2(v0.x, v0.y);
                    Ku[base + (tile + 1) * 128 + ln * 4 + reg] = pack_h2(v1.x, v1.y);
                } else {
                    // B-frag-major V (n=d, k=key): 4 scalar half stores
                    __half* vb = Vh + (size_t)bh * 131072;
                    #pragma unroll
                    for (int e = 0; e < 4; ++e) {
                        const int key = tt + (e >> 1) * 8;
                        const int d   = dd + (e & 1);
                        const float val = (e == 0) ? v0.x : (e == 1) ? v0.y
                                        : (e == 2) ? v1.x : v1.y;
                        const int kk = key & 31;
                        const size_t o = ((size_t)(key >> 5) * 8 + (d >> 3)) * 128
                                       + ((d & 7) * 4 + ((kk >> 1) & 3)) * 4
                                       + ((kk >> 4) & 1) * 2 + ((kk >> 3) & 1);
                        vb[o * 2 + (key & 1)] = __float2half_rn(val);
                    }
                }
            }
        }
    }
}

// ---------------------------------------------------------------------------
// fp16 flash attention, fully fragment-resident:
// Q fragments direct LDG.128 (A-frag-major global), K/V fragments LDS.128
// from B-frag-major smem tiles, P KEPT IN REGISTERS (S C-frag == PV A-frag).
// Double-buffered KV (16 KB/stage, 32 KB total), single barrier per tile.
// ---------------------------------------------------------------------------
#define KV_U32 4096
#define ATTN_SMEM (2 * KV_U32 * 4)   // 32768

__global__ void __launch_bounds__(256, 2) attn_f16_kernel(uint32_t* __restrict__ Yu)
{
    extern __shared__ float smf[];
    uint32_t* KV = (uint32_t*)smf;

    const int qt  = gridDim.x - 1 - blockIdx.x;
    const int bh  = blockIdx.y;
    const int b   = bh >> 4, h = bh & 15;
    const int tid = threadIdx.x;
    const int lane = tid & 31;
    const int w    = tid >> 5;
    const int qr   = lane >> 2;
    const int qc   = lane & 3;

    const uint32_t* Ku = (const uint32_t*)g_k + (size_t)bh * 65536;
    const uint32_t* Vu = (const uint32_t*)g_v + (size_t)bh * 65536;
    const uint32_t kv_b = cvta_smem(KV);

    // Prologue: issue KV tile 0 into stage 0
    {
        cp_async16(kv_b + tid * 16,              Ku + tid * 4);          // K kt0 (kb0,half0)
        cp_async16(kv_b + 4096 + tid * 16,       Ku + 2048 + tid * 4);   // K kt1
        cp_async16(kv_b + 8192 + tid * 16,       Vu + tid * 4);          // V k32=0
        cp_async16(kv_b + 12288 + tid * 16,      Vu + 1024 + tid * 4);   // V k32=1
        cp_commit();
    }

    // Q fragments: 4 direct LDG.128 (A-frag-major, pre-scaled)
    uint32_t qf[4][4];
    {
        const uint32_t* qb = (const uint32_t*)g_q + ((size_t)(bh * 16 + qt)) * 2 * 2048;
        #pragma unroll
        for (int ks = 0; ks < 4; ++ks)
            *(uint4*)qf[ks] = *(const uint4*)(qb + (ks >> 1) * 2048
                                              + (w * 2 + (ks & 1)) * 128 + lane * 4);
    }

    float m0 = NEG_BIG, m1 = NEG_BIG, l0 = 0.f, l1 = 0.f;
    float oacc[8][4];
    #pragma unroll
    for (int nt = 0; nt < 8; ++nt)
        #pragma unroll
        for (int r = 0; r < 4; ++r) oacc[nt][r] = 0.f;

    const int row0 = w * 16 + qr;
    const int jmax = 2 * qt + 1;

    for (int j = 0; j <= jmax; ++j) {
        cp_wait0();
        __syncthreads();   // stage (j&1) data visible; all warps done with j-1

        if (j + 1 <= jmax) {
            const int jn = j + 1;
            const uint32_t stg = kv_b + (jn & 1) * KV_U32 * 4;
            const uint32_t* Kc = Ku + ((jn >> 1) * 2) * 2048 + (jn & 1) * 1024;
            const uint32_t* Vc = Vu + (size_t)(2 * jn) * 1024;
            cp_async16(stg + tid * 16,         Kc + tid * 4);
            cp_async16(stg + 4096 + tid * 16,  Kc + 2048 + tid * 4);
            cp_async16(stg + 8192 + tid * 16,  Vc + tid * 4);
            cp_async16(stg + 12288 + tid * 16, Vc + 1024 + tid * 4);
            cp_commit();
        }

        const uint32_t* Ksm = KV + (j & 1) * KV_U32;
        const uint32_t* Vsm = Ksm + 2048;

        int ntmax = 8;
        if (j == 2 * qt) {
            ntmax = 2 * w + 2; if (ntmax > 8) ntmax = 8;
        } else if (j == 2 * qt + 1) {
            ntmax = 2 * w - 6; if (ntmax < 0) ntmax = 0;
        }

        if (ntmax > 0) {
            // ---- S = Q K^T ----
            float sacc[8][4];
            #pragma unroll
            for (int nt = 0; nt < 8; ++nt)
                #pragma unroll
                for (int r = 0; r < 4; ++r) sacc[nt][r] = 0.f;

            #pragma unroll
            for (int nt = 0; nt < 8; ++nt) {
                if (nt < ntmax) {
                    uint4 k0 = *(const uint4*)(Ksm + nt * 128 + lane * 4);
                    uint4 k1 = *(const uint4*)(Ksm + 1024 + nt * 128 + lane * 4);
                    uint32_t b0[2] = { k0.x, k0.y };
                    uint32_t b1[2] = { k0.z, k0.w };
                    uint32_t b2[2] = { k1.x, k1.y };
                    uint32_t b3[2] = { k1.z, k1.w };
                    mma_f16(sacc[nt], qf[0], b0);
                    mma_f16(sacc[nt], qf[1], b1);
                    mma_f16(sacc[nt], qf[2], b2);
                    mma_f16(sacc[nt], qf[3], b3);
                }
            }

            // ---- Causal mask (diagonal tiles) ----
            if (j >= 2 * qt) {
                const int rel = (j - 2 * qt) * 64;
                #pragma unroll
                for (int nt = 0; nt < 8; ++nt) {
                    if (nt < ntmax) {
                        const int col = rel + nt * 8 + qc * 2;
                        if (col     > row0)     sacc[nt][0] = NEG_BIG;
                        if (col + 1 > row0)     sacc[nt][1] = NEG_BIG;
                        if (col     > row0 + 8) sacc[nt][2] = NEG_BIG;
                        if (col + 1 > row0 + 8) sacc[nt][3] = NEG_BIG;
                    }
                }
            }

            // ---- Online softmax; P packed straight into registers ----
            float rmax0 = NEG_BIG, rmax1 = NEG_BIG;
            #pragma unroll
            for (int nt = 0; nt < 8; ++nt) {
                if (nt < ntmax) {
                    rmax0 = fmaxf(rmax0, fmaxf(sacc[nt][0], sacc[nt][1]));
                    rmax1 = fmaxf(rmax1, fmaxf(sacc[nt][2], sacc[nt][3]));
                }
            }
            rmax0 = fmaxf(rmax0, __shfl_xor_sync(0xffffffffu, rmax0, 1));
            rmax0 = fmaxf(rmax0, __shfl_xor_sync(0xffffffffu, rmax0, 2));
            rmax1 = fmaxf(rmax1, __shfl_xor_sync(0xffffffffu, rmax1, 1));
            rmax1 = fmaxf(rmax1, __shfl_xor_sync(0xffffffffu, rmax1, 2));

            const float mn0 = fmaxf(m0, rmax0);
            const float mn1 = fmaxf(m1, rmax1);
            const float al0 = __expf(m0 - mn0);
            const float al1 = __expf(m1 - mn1);

            uint32_t pf[4][4];
            float rs0 = 0.f, rs1 = 0.f;
            #pragma unroll
            for (int nt = 0; nt < 8; ++nt) {
                if (nt < ntmax) {
                    const float p00 = __expf(sacc[nt][0] - mn0);
                    const float p01 = __expf(sacc[nt][1] - mn0);
                    const float p10 = __expf(sacc[nt][2] - mn1);
                    const float p11 = __expf(sacc[nt][3] - mn1);
                    rs0 += p00 + p01;
                    rs1 += p10 + p11;
                    const int ks = nt >> 1;
                    const int rb = (nt & 1) * 2;
                    pf[ks][rb]     = pack_h2(p00, p01);
                    pf[ks][rb + 1] = pack_h2(p10, p11);
                }
            }
            rs0 += __shfl_xor_sync(0xffffffffu, rs0, 1);
            rs0 += __shfl_xor_sync(0xffffffffu, rs0, 2);
            rs1 += __shfl_xor_sync(0xffffffffu, rs1, 1);
            rs1 += __shfl_xor_sync(0xffffffffu, rs1, 2);

            l0 = l0 * al0 + rs0;
            l1 = l1 * al1 + rs1;
            m0 = mn0;
            m1 = mn1;

            #pragma unroll
            for (int nt = 0; nt < 8; ++nt) {
                oacc[nt][0] *= al0; oacc[nt][1] *= al0;
                oacc[nt][2] *= al1; oacc[nt][3] *= al1;
            }

            // ---- O += P V (P in registers; V B-frags from smem) ----
            const int kmax = ntmax >> 1;
            #pragma unroll
            for (int nt = 0; nt < 8; ++nt) {
                uint4 v0 = *(const uint4*)(Vsm + nt * 128 + lane * 4);
                uint32_t b0[2] = { v0.x, v0.y };
                uint32_t b1[2] = { v0.z, v0.w };
                mma_f16(oacc[nt], pf[0], b0);
                if (1 < kmax) mma_f16(oacc[nt], pf[1], b1);
                if (2 < kmax) {
                    uint4 v1 = *(const uint4*)(Vsm + 1024 + nt * 128 + lane * 4);
                    uint32_t b2[2] = { v1.x, v1.y };
                    uint32_t b3[2] = { v1.z, v1.w };
                    mma_f16(oacc[nt], pf[2], b2);
                    if (3 < kmax) mma_f16(oacc[nt], pf[3], b3);
                }
            }
        }
    }

    // Epilogue: normalize, pack fp16, scatter into fragment-major y
    const float inv0 = 1.0f / l0;
    const float inv1 = 1.0f / l1;
    const int mb = b * 16 + qt;
    #pragma unroll
    for (int nt = 0; nt < 8; ++nt) {
        const int ktc = h * 2 + (nt >> 2);
        const int kstep = (nt >> 1) & 1;
        const int rb = (nt & 1) * 2;
        uint32_t* blk = Yu + ((size_t)(mb * 32 + ktc) * 16 + (w * 2 + kstep)) * 128 + lane * 4;
        blk[rb]     = pack_h2(oacc[nt][0] * inv0, oacc[nt][1] * inv0);
        blk[rb + 1] = pack_h2(oacc[nt][2] * inv1, oacc[nt][3] * inv1);
    }
}

// ---------------------------------------------------------------------------
extern "C" void kernel_launch(void* const* d_in, const int* in_sizes, int n_in,
                              void* d_out, int out_size)
{
    const float* x      = (const float*)d_in[0];
    const float* w_attn = (const float*)d_in[1];
    const float* b_attn = (const float*)d_in[2];
    const float* w_proj = (const float*)d_in[3];
    const float* b_proj = (const float*)d_in[4];
    float* out = (float*)d_out;

    void *yv, *xv, *wav, *wpv;
    cudaGetSymbolAddress(&yv,  g_y);
    cudaGetSymbolAddress(&xv,  g_xr);
    cudaGetSymbolAddress(&wav, g_war);
    cudaGetSymbolAddress(&wpv, g_wpr);
    uint32_t* yu  = (uint32_t*)yv;
    uint32_t* xr  = (uint32_t*)xv;
    uint32_t* war = (uint32_t*)wav;
    uint32_t* wpr = (uint32_t*)wpv;

    cudaFuncSetAttribute(gemm_f16_kernel<1>,
                         cudaFuncAttributeMaxDynamicSharedMemorySize, GEMM_SMEM);
    cudaFuncSetAttribute(gemm_f16_kernel<0>,
                         cudaFuncAttributeMaxDynamicSharedMemorySize, GEMM_SMEM);
    cudaFuncSetAttribute(attn_f16_kernel,
                         cudaFuncAttributeMaxDynamicSharedMemorySize, ATTN_SMEM);

    // 0) Prepass: permute + fp16-round
    permA_kernel<<<dim3(32, 64), 256>>>(x,      xr,  C_DIM);
    permB_kernel<<<dim3(32, 24), 256>>>(w_attn, war, C_DIM);
    permB_kernel<<<dim3(32,  8), 256>>>(w_proj, wpr, C_DIM);

    // 1) QKV projection; epilogue emits fragment-major Q(scaled)/K/V
    dim3 g1(QKV_N / 128, M_ROWS / 128);   // 24 x 64
    gemm_f16_kernel<1><<<g1, 256, GEMM_SMEM>>>(xr, war, b_attn, nullptr, QKV_N, C_DIM);

    // 2) Causal flash attention -> y fragment-major fp16
    dim3 g2(T_ / 128, B_ * H_);           // 16 x 64
    attn_f16_kernel<<<g2, 256, ATTN_SMEM>>>(yu);

    // 3) Output projection -> d_out fp32
    dim3 g3(C_DIM / 128, M_ROWS / 128);   // 8 x 64
    gemm_f16_kernel<0><<<g3, 256, GEMM_SMEM>>>(yu, wpr, b_proj, out, C_DIM, C_DIM);
}